// round 15
// baseline (speedup 1.0000x reference)
#include <cuda_runtime.h>
#include <cuda_bf16.h>
#include <cstdint>

typedef unsigned int u32;

#define HH 300
#define WW 300
#define TW 32
#define GX 10

// ---- conv1 tile: 32 x 8 ----
#define TH1 8
#define INH1 10
#define XP 344                 // x-tile channel-pair stride (344%32==24 -> conflict-free)
#define GY1 38
// us array widths (pooled cols + 1 zero slot)
#define W5 9
#define W10 6
#define W15 5
// smem u32 offsets (conv1)
#define XH_OFF 0
#define XL_OFF (4*XP)                    // 1376
#define US5H_OFF (2*4*XP)                // 2752
#define US5L_OFF (US5H_OFF + 4*10*W5)    // +360
#define US10H_OFF (US5L_OFF + 4*10*W5)
#define US10L_OFF (US10H_OFF + 4*10*W10)
#define US15H_OFF (US10L_OFF + 4*10*W10)
#define US15L_OFF (US15H_OFF + 4*10*W15)
#define BSM1_OFF (US15L_OFF + 4*10*W15)  // 4352
#define NFRAG1 27
#define BIAS1_OFF (BSM1_OFF + NFRAG1*128)
#define SMEM1_U32 (BIAS1_OFF + 32)

// ---- conv2 tile: 32 x 16 ----
#define TH2 16
#define INH2 18
#define RS2 35                 // row stride (35%32==3, coprime -> conflict-free A loads)
#define CS2 (INH2*RS2)         // 630
#define GY2 19
#define NBLK (GX*GY2*32)       // 6080
#define K2 224
#define K2R 216
#define STEPS2 14
#define NT2 2
#define BSM2_OFF (24*CS2)                 // 15120
#define KOFF_OFF (BSM2_OFF + STEPS2*NT2*2*32*2)
#define BIAS2_OFF (KOFF_OFF + K2)
#define RED2_OFF (BIAS2_OFF + 16)
#define SMEM2_U32 (RED2_OFF + 128 + 8)

// ---------------- device scratch ----------------
__device__ u32   g_pk[32u*24u*HH*WW];
__device__ float p5f[32*8*60*60];
__device__ float p10f[32*8*30*30];
__device__ float p15f[32*8*20*20];
__device__ u32   bfrag1[NFRAG1*128];
__device__ u32   bfrag2[STEPS2*NT2*2*32*2];
__device__ float part_buf[16*NBLK];   // TRANSPOSED: [v][blin] for coalesced stats
__device__ float bn_buf[16];

// ---------------- helpers ----------------
__device__ __forceinline__ u32 pack_split(float v) {
    __nv_bfloat16 h = __float2bfloat16(v);
    float hf = __bfloat162float(h);
    __nv_bfloat16 l = __float2bfloat16(v - hf);
    return ((u32)__bfloat16_as_ushort(h) << 16) | (u32)__bfloat16_as_ushort(l);
}
__device__ __forceinline__ void mma_bf16(float* d, u32 a0, u32 a1, u32 a2, u32 a3,
                                         u32 b0, u32 b1) {
    asm volatile(
        "mma.sync.aligned.m16n8k16.row.col.f32.bf16.bf16.f32 "
        "{%0,%1,%2,%3},{%4,%5,%6,%7},{%8,%9},{%0,%1,%2,%3};"
        : "+f"(d[0]), "+f"(d[1]), "+f"(d[2]), "+f"(d[3])
        : "r"(a0), "r"(a1), "r"(a2), "r"(a3), "r"(b0), "r"(b1));
}
// truncation split of (v0,v1) into hi word + rounded-lo word
__device__ __forceinline__ void split2(float v0, float v1, u32& H, u32& L) {
    u32 u0 = __float_as_uint(v0), u1 = __float_as_uint(v1);
    H = __byte_perm(u0, u1, 0x7632);
    float h0 = __uint_as_float(u0 & 0xFFFF0000u);
    float h1 = __uint_as_float(u1 & 0xFFFF0000u);
    __nv_bfloat162 Ll = __floats2bfloat162_rn(v0 - h0, v1 - h1);
    L = *reinterpret_cast<u32*>(&Ll);
}

// ---------------- pools (fp32) ----------------
__global__ void k_pool5(const float* __restrict__ x) {
    int i = blockIdx.x * blockDim.x + threadIdx.x;
    if (i >= 32*8*60*60) return;
    int px = i % 60; int t = i / 60;
    int py = t % 60; t /= 60;
    int c  = t % 8;  int b = t / 8;
    const float* base = x + ((size_t)(b*8 + c)*HH + py*5)*WW + px*5;
    float s = 0.f;
    #pragma unroll
    for (int r = 0; r < 5; r++)
        #pragma unroll
        for (int q = 0; q < 5; q++) s += base[r*WW + q];
    p5f[i] = s * (1.0f/25.0f);
}
__global__ void k_poolrest() {
    int i = blockIdx.x * blockDim.x + threadIdx.x;
    if (i < 32*8*30*30) {
        int px = i % 30; int t = i / 30;
        int py = t % 30; t /= 30;
        int c  = t % 8;  int b = t / 8;
        const float* base = p5f + ((b*8 + c)*60 + py*2)*60 + px*2;
        p10f[i] = (base[0] + base[1] + base[60] + base[61]) * 0.25f;
    }
    int j = i - 32*8*30*30;
    if (j >= 0 && j < 32*8*20*20) {
        int px = j % 20; int t = j / 20;
        int py = t % 20; t /= 20;
        int c  = t % 8;  int b = t / 8;
        const float* base = p5f + ((b*8 + c)*60 + py*3)*60 + px*3;
        float s = 0.f;
        #pragma unroll
        for (int r = 0; r < 3; r++)
            #pragma unroll
            for (int q = 0; q < 3; q++) s += base[r*60 + q];
        p15f[j] = s * (1.0f/9.0f);
    }
}

// ---------------- weight fragment prep ----------------
__global__ void k_prepw(const float* __restrict__ w5,  const float* __restrict__ w10,
                        const float* __restrict__ w15, const float* __restrict__ gw,
                        const float* __restrict__ mw) {
    int tid = blockIdx.x * blockDim.x + threadIdx.x;
    for (int e = tid; e < NFRAG1*128; e += blockDim.x * gridDim.x) {
        int blk = e >> 7;
        int rem = e & 127;
        int sp = rem >> 6;
        int lane = (rem & 63) >> 1;
        int r = rem & 1;
        int br = blk / 9, tap = blk % 9;
        const float* w = (br == 0) ? w5 : (br == 1 ? w10 : w15);
        int n = lane >> 2;
        int k0 = (lane & 3)*2 + r*8;
        float v0 = w[(n*16 + k0    )*9 + tap];
        float v1 = w[(n*16 + k0 + 1)*9 + tap];
        u32 word;
        if (sp == 0) {
            word = ((u32)__bfloat16_as_ushort(__float2bfloat16(v1)) << 16)
                 |  (u32)__bfloat16_as_ushort(__float2bfloat16(v0));
        } else {
            float h0 = __bfloat162float(__float2bfloat16(v0));
            float h1 = __bfloat162float(__float2bfloat16(v1));
            word = ((u32)__bfloat16_as_ushort(__float2bfloat16(v1 - h1)) << 16)
                 |  (u32)__bfloat16_as_ushort(__float2bfloat16(v0 - h0));
        }
        bfrag1[e] = word;
    }
    for (int e = tid; e < STEPS2*NT2*2*32*2; e += blockDim.x * gridDim.x) {
        int r = e & 1; int t = (e >> 1) & 31; int sp = (e >> 6) & 1;
        int nt = (e >> 7) % NT2; int step = (e >> 7) / NT2;
        int n = nt*8 + t/4;
        int k0 = step*16 + (t & 3)*2 + r*8;
        float v0 = 0.f, v1 = 0.f;
        if (k0 < K2R)
            v0 = (n < 8) ? gw[(n*24 + k0/9)*9 + k0%9] : mw[((n-8)*24 + k0/9)*9 + k0%9];
        int k1 = k0 + 1;
        if (k1 < K2R)
            v1 = (n < 8) ? gw[(n*24 + k1/9)*9 + k1%9] : mw[((n-8)*24 + k1/9)*9 + k1%9];
        u32 w;
        if (sp == 0) {
            w = ((u32)__bfloat16_as_ushort(__float2bfloat16(v1)) << 16)
              |  (u32)__bfloat16_as_ushort(__float2bfloat16(v0));
        } else {
            float h0 = __bfloat162float(__float2bfloat16(v0));
            float h1 = __bfloat162float(__float2bfloat16(v1));
            w = ((u32)__bfloat16_as_ushort(__float2bfloat16(v1 - h1)) << 16)
              |  (u32)__bfloat16_as_ushort(__float2bfloat16(v0 - h0));
        }
        bfrag2[e] = w;
    }
}

// ---------------- conv1: branch GEMMs, pooled-col up arrays ----------------
// occupancy 4 blocks/SM (regs capped at 64)
__global__ void __launch_bounds__(256, 4)
k_conv1(const float* __restrict__ x,
        const float* __restrict__ b5, const float* __restrict__ b10,
        const float* __restrict__ b15) {
    extern __shared__ u32 smu[];
    float* bias = (float*)(smu + BIAS1_OFF);

    int tid = threadIdx.x;
    int b  = blockIdx.z;
    int x0 = blockIdx.x * TW, y0 = blockIdx.y * TH1;

    int xm = (x0 > 1) ? (x0 - 1) : 0;
    int pc05 = xm/5, pc010 = xm/10, pc015 = xm/15;

    // x channels: 4 c2-pairs x 340 pixels
    for (int i = tid; i < 4*340; i += 256) {
        int c2 = i / 340, pix = i - c2*340;
        int ty = pix / 34, tx = pix - ty*34;
        int gy = y0 - 1 + ty, gx = x0 - 1 + tx;
        float v0 = 0.f, v1 = 0.f;
        if ((unsigned)gy < HH && (unsigned)gx < WW) {
            const float* p = x + ((size_t)(b*8 + 2*c2)*HH + gy)*WW + gx;
            v0 = p[0]; v1 = p[(size_t)HH*WW];
        }
        u32 H, L; split2(v0, v1, H, L);
        smu[XH_OFF + c2*XP + pix] = H;
        smu[XL_OFF + c2*XP + pix] = L;
    }
    // pooled-col up arrays: 800 elements total
    for (int e = tid; e < 800; e += 256) {
        float v0 = 0.f, v1 = 0.f;
        int hoff, loff, idx;
        if (e < 360) {                       // us5: [c2][10][9]
            int c2 = e / 90, rm = e - c2*90;
            int ty = rm / W5, pc = rm - ty*W5;
            int gy = y0 - 1 + ty, pcg = pc05 + pc;
            if ((unsigned)gy < HH && pc < 8 && pcg < 60) {
                const float* p = p5f + ((b*8 + 2*c2)*60 + gy/5)*60 + pcg;
                v0 = p[0]; v1 = p[3600];
            }
            hoff = US5H_OFF; loff = US5L_OFF; idx = e;
        } else if (e < 600) {                // us10: [c2][10][6]
            int e2 = e - 360;
            int c2 = e2 / 60, rm = e2 - c2*60;
            int ty = rm / W10, pc = rm - ty*W10;
            int gy = y0 - 1 + ty, pcg = pc010 + pc;
            if ((unsigned)gy < HH && pc < 5 && pcg < 30) {
                const float* p = p10f + ((b*8 + 2*c2)*30 + gy/10)*30 + pcg;
                v0 = p[0]; v1 = p[900];
            }
            hoff = US10H_OFF; loff = US10L_OFF; idx = e2;
        } else {                             // us15: [c2][10][5]
            int e3 = e - 600;
            int c2 = e3 / 50, rm = e3 - c2*50;
            int ty = rm / W15, pc = rm - ty*W15;
            int gy = y0 - 1 + ty, pcg = pc015 + pc;
            if ((unsigned)gy < HH && pc < 4 && pcg < 20) {
                const float* p = p15f + ((b*8 + 2*c2)*20 + gy/15)*20 + pcg;
                v0 = p[0]; v1 = p[400];
            }
            hoff = US15H_OFF; loff = US15L_OFF; idx = e3;
        }
        u32 H, L; split2(v0, v1, H, L);
        smu[hoff + idx] = H;
        smu[loff + idx] = L;
    }
    for (int i = tid; i < NFRAG1*128; i += 256) smu[BSM1_OFF + i] = bfrag1[i];
    if (tid < 24)
        bias[tid] = (tid < 8) ? b5[tid] : (tid < 16 ? b10[tid-8] : b15[tid-16]);
    __syncthreads();

    int lane = tid & 31, w = tid >> 5;
    int g = lane >> 2, tg = lane & 3;
    int s = w >> 2, wr = w & 3;
    int ry0 = wr*2;

    // per-lane packed pooled cols (byte q = tap col q), zero slot when invalid
    int gxa = x0 - 1 + s*16 + g;
    u32 pA[3] = {0,0,0}, pB[3] = {0,0,0};
    #pragma unroll
    for (int q = 0; q < 3; q++) {
        int xa = gxa + q, xb = xa + 8;
        u32 a5  = ((unsigned)xa < WW) ? (u32)(xa/5  - pc05)  : 8u;
        u32 b5_ = ((unsigned)xb < WW) ? (u32)(xb/5  - pc05)  : 8u;
        u32 a10 = ((unsigned)xa < WW) ? (u32)(xa/10 - pc010) : 5u;
        u32 b10_= ((unsigned)xb < WW) ? (u32)(xb/10 - pc010) : 5u;
        u32 a15 = ((unsigned)xa < WW) ? (u32)(xa/15 - pc015) : 4u;
        u32 b15_= ((unsigned)xb < WW) ? (u32)(xb/15 - pc015) : 4u;
        pA[0] |= a5  << (q*8); pB[0] |= b5_  << (q*8);
        pA[1] |= a10 << (q*8); pB[1] |= b10_ << (q*8);
        pA[2] |= a15 << (q*8); pB[2] |= b15_ << (q*8);
    }

    const int USW[3]  = {W5, W10, W15};
    const int USH[3]  = {US5H_OFF, US10H_OFF, US15H_OFF};
    const int USL[3]  = {US5L_OFF, US10L_OFF, US15L_OFF};

    float d[2][3][4];
    #pragma unroll
    for (int j = 0; j < 2; j++)
        #pragma unroll
        for (int br = 0; br < 3; br++)
            #pragma unroll
            for (int q = 0; q < 4; q++) d[j][br][q] = 0.f;

    #pragma unroll
    for (int tapr = 0; tapr < 3; tapr++) {
        #pragma unroll
        for (int tapc = 0; tapc < 3; tapc++) {
            int tap = tapr*3 + tapc;
            uint2 bh[3], bl[3];
            #pragma unroll
            for (int br = 0; br < 3; br++) {
                int bb = BSM1_OFF + (br*9 + tap)*128 + lane*2;
                bh[br] = *reinterpret_cast<const uint2*>(&smu[bb]);
                bl[br] = *reinterpret_cast<const uint2*>(&smu[bb + 64]);
            }
            #pragma unroll
            for (int j = 0; j < 2; j++) {
                int ty = ry0 + j + tapr;
                int xi = tg*XP + ty*34 + s*16 + g + tapc;
                u32 xh0 = smu[XH_OFF + xi], xh1 = smu[XH_OFF + xi + 8];
                u32 xl0 = smu[XL_OFF + xi], xl1 = smu[XL_OFF + xi + 8];
                #pragma unroll
                for (int br = 0; br < 3; br++) {
                    int pa = (pA[br] >> (tapc*8)) & 0xFF;
                    int pb = (pB[br] >> (tapc*8)) & 0xFF;
                    int ub = (tg*10 + ty)*USW[br];
                    u32 uh0 = smu[USH[br] + ub + pa];
                    u32 uh1 = smu[USH[br] + ub + pb];
                    u32 ul0 = smu[USL[br] + ub + pa];
                    u32 ul1 = smu[USL[br] + ub + pb];
                    mma_bf16(d[j][br], xh0, xh1, uh0, uh1, bh[br].x, bh[br].y);
                    mma_bf16(d[j][br], xh0, xh1, uh0, uh1, bl[br].x, bl[br].y);
                    mma_bf16(d[j][br], xl0, xl1, ul0, ul1, bh[br].x, bh[br].y);
                }
            }
        }
    }

    // epilogue: +bias, split-pack, store to g_pk
    #pragma unroll
    for (int j = 0; j < 2; j++) {
        int py = y0 + ry0 + j;
        if (py >= HH) continue;
        int px0 = x0 + s*16 + g;
        #pragma unroll
        for (int br = 0; br < 3; br++) {
            int oc = br*8 + 2*tg;
            float bv0 = bias[oc], bv1 = bias[oc+1];
            size_t r0 = ((size_t)(b*24 + oc  )*HH + py)*WW;
            size_t r1 = ((size_t)(b*24 + oc+1)*HH + py)*WW;
            if (px0 < WW) {
                g_pk[r0 + px0] = pack_split(d[j][br][0] + bv0);
                g_pk[r1 + px0] = pack_split(d[j][br][1] + bv1);
            }
            if (px0 + 8 < WW) {
                g_pk[r0 + px0+8] = pack_split(d[j][br][2] + bv0);
                g_pk[r1 + px0+8] = pack_split(d[j][br][3] + bv1);
            }
        }
    }
}

// ---------------- conv2: gated pair + BN partials ----------------
// element-wise COALESCED loader + padded smem strides (RS2=35)
__global__ void __launch_bounds__(256, 2)
k_conv2(const float* __restrict__ gb, const float* __restrict__ mb,
        float* __restrict__ out) {
    extern __shared__ u32 smu[];
    u32* tile = smu;
    u32* bsm  = smu + BSM2_OFF;
    int* koffs = (int*)(smu + KOFF_OFF);
    float* bias = (float*)(smu + BIAS2_OFF);
    float* red  = (float*)(smu + RED2_OFF);

    int tid = threadIdx.x;
    int b  = blockIdx.z;
    int x0 = blockIdx.x * TW, y0 = blockIdx.y * TH2;

    // element-wise coalesced tile load (consecutive tid -> consecutive gx)
    for (int i = tid; i < 24*18*34; i += 256) {
        int tx = i % 34; int t = i / 34;
        int ty = t % 18; int c = t / 18;
        int gy = y0 - 1 + ty, gx = x0 - 1 + tx;
        u32 v = 0u;
        if ((unsigned)gy < HH && (unsigned)gx < WW)
            v = g_pk[((size_t)(b*24 + c)*HH + gy)*WW + gx];
        tile[c*CS2 + ty*RS2 + tx] = v;
    }
    for (int i = tid; i < STEPS2*NT2*2*32*2; i += 256) bsm[i] = bfrag2[i];
    for (int k = tid; k < K2; k += 256)
        koffs[k] = (k < K2R) ? (k/9)*CS2 + ((k%9)/3)*RS2 + (k%3) : 0;
    if (tid < 16) bias[tid] = (tid < 8) ? gb[tid] : mb[tid-8];
    __syncthreads();

    int lane = tid & 31, w = tid >> 5;
    int g = lane >> 2, tg = lane & 3;
    int s = w >> 2, wr = w & 3;

    float s0 = 0.f, s1 = 0.f, q0 = 0.f, q1 = 0.f;

    for (int p = 0; p < 2; p++) {
        int ry0 = wr*4 + p*2;
        int baseA = ry0*RS2 + s*16 + g;
        float d[2][NT2][4];
        #pragma unroll
        for (int j = 0; j < 2; j++)
            #pragma unroll
            for (int nt = 0; nt < NT2; nt++)
                #pragma unroll
                for (int q = 0; q < 4; q++) d[j][nt][q] = 0.f;

        for (int step = 0; step < STEPS2; step++) {
            int kb = step*16 + 2*tg;
            int o0 = koffs[kb], o1 = koffs[kb+1], o2 = koffs[kb+8], o3 = koffs[kb+9];
            u32 ah[2][4], al[2][4];
            #pragma unroll
            for (int j = 0; j < 2; j++) {
                int ba = baseA + j*RS2;
                u32 e00 = tile[ba + o0],   e01 = tile[ba + o1];
                u32 e02 = tile[ba + o2],   e03 = tile[ba + o3];
                u32 e10 = tile[ba+8 + o0], e11 = tile[ba+8 + o1];
                u32 e12 = tile[ba+8 + o2], e13 = tile[ba+8 + o3];
                ah[j][0] = __byte_perm(e00, e01, 0x7632);
                ah[j][1] = __byte_perm(e10, e11, 0x7632);
                ah[j][2] = __byte_perm(e02, e03, 0x7632);
                ah[j][3] = __byte_perm(e12, e13, 0x7632);
                al[j][0] = __byte_perm(e00, e01, 0x5410);
                al[j][1] = __byte_perm(e10, e11, 0x5410);
                al[j][2] = __byte_perm(e02, e03, 0x5410);
                al[j][3] = __byte_perm(e12, e13, 0x5410);
            }
            #pragma unroll
            for (int nt = 0; nt < NT2; nt++) {
                int bi = ((step*NT2 + nt)*2)*64 + lane*2;
                uint2 bh = *reinterpret_cast<const uint2*>(&bsm[bi]);
                uint2 bl = *reinterpret_cast<const uint2*>(&bsm[bi + 64]);
                #pragma unroll
                for (int j = 0; j < 2; j++) {
                    mma_bf16(d[j][nt], ah[j][0], ah[j][1], ah[j][2], ah[j][3], bh.x, bh.y);
                    mma_bf16(d[j][nt], ah[j][0], ah[j][1], ah[j][2], ah[j][3], bl.x, bl.y);
                    mma_bf16(d[j][nt], al[j][0], al[j][1], al[j][2], al[j][3], bh.x, bh.y);
                }
            }
        }

        int oc0 = 2*tg;
        float bg0 = bias[oc0], bg1 = bias[oc0+1];
        float bm0 = bias[8+oc0], bm1 = bias[8+oc0+1];
        #pragma unroll
        for (int j = 0; j < 2; j++) {
            int py = y0 + ry0 + j;
            bool vy = (py < HH);
            int px0 = x0 + s*16 + g;
            size_t r0 = ((size_t)(b*8 + oc0  )*HH + py)*WW;
            size_t r1 = ((size_t)(b*8 + oc0+1)*HH + py)*WW;
            #pragma unroll
            for (int h = 0; h < 2; h++) {
                int px = px0 + h*8;
                bool vld = vy && (px < WW);
                float ga = d[j][0][2*h]   + bg0;
                float gb_ = d[j][0][2*h+1] + bg1;
                float ma = d[j][1][2*h]   + bm0;
                float mb_ = d[j][1][2*h+1] + bm1;
                float y0v = ga / (1.f + __expf(-ma));
                float y1v = gb_ / (1.f + __expf(-mb_));
                if (vld) {
                    out[r0 + px] = y0v;
                    out[r1 + px] = y1v;
                    s0 += y0v; q0 += y0v*y0v;
                    s1 += y1v; q1 += y1v*y1v;
                }
            }
        }
    }

    #pragma unroll
    for (int dlt = 4; dlt < 32; dlt <<= 1) {
        s0 += __shfl_xor_sync(0xffffffffu, s0, dlt);
        s1 += __shfl_xor_sync(0xffffffffu, s1, dlt);
        q0 += __shfl_xor_sync(0xffffffffu, q0, dlt);
        q1 += __shfl_xor_sync(0xffffffffu, q1, dlt);
    }
    if (g == 0) {
        red[w*16 + 2*tg]     = s0;
        red[w*16 + 2*tg + 1] = s1;
        red[w*16 + 8 + 2*tg]     = q0;
        red[w*16 + 8 + 2*tg + 1] = q1;
    }
    __syncthreads();
    if (tid < 16) {
        float t = 0.f;
        #pragma unroll
        for (int w2 = 0; w2 < 8; w2++) t += red[w2*16 + tid];
        int blin = (b*GY2 + blockIdx.y)*GX + blockIdx.x;
        part_buf[tid*NBLK + blin] = t;   // transposed layout
    }
}

// ---------------- BN stats: 16 warps, coalesced, deterministic ----------------
__global__ void k_stats(const float* __restrict__ gamma, const float* __restrict__ beta) {
    __shared__ double sums[16];
    int tid = threadIdx.x;
    int w = tid >> 5, lane = tid & 31;
    // warp w sums part_buf[w*NBLK .. w*NBLK+NBLK)
    double a0 = 0.0, a1 = 0.0, a2 = 0.0, a3 = 0.0;
    const float* src = part_buf + w*NBLK;
    for (int i = lane; i < NBLK; i += 128) {
        a0 += (double)src[i];
        if (i + 32 < NBLK) a1 += (double)src[i + 32];
        if (i + 64 < NBLK) a2 += (double)src[i + 64];
        if (i + 96 < NBLK) a3 += (double)src[i + 96];
    }
    double acc = (a0 + a1) + (a2 + a3);
    #pragma unroll
    for (int d = 16; d > 0; d >>= 1)
        acc += __shfl_xor_sync(0xffffffffu, acc, d);
    if (lane == 0) sums[w] = acc;
    __syncthreads();
    if (tid < 8) {
        const double N = 2880000.0;
        double mean = sums[tid] / N;
        double ex2  = sums[8 + tid] / N;
        double var  = ex2 - mean * mean;
        double scale = (double)gamma[tid] / sqrt(var + 1e-5);
        double shift = (double)beta[tid] - mean * scale;
        bn_buf[tid]     = (float)scale;
        bn_buf[8 + tid] = (float)shift;
    }
}

// ---------------- normalize ----------------
__global__ void k_norm(float* __restrict__ out) {
    int i = blockIdx.x * blockDim.x + threadIdx.x;
    if (i >= 5760000) return;
    int c = (i / 22500) & 7;
    float sc = bn_buf[c], sh = bn_buf[8 + c];
    float4 v = reinterpret_cast<float4*>(out)[i];
    v.x = v.x * sc + sh;
    v.y = v.y * sc + sh;
    v.z = v.z * sc + sh;
    v.w = v.w * sc + sh;
    reinterpret_cast<float4*>(out)[i] = v;
}

// ---------------- launch ----------------
extern "C" void kernel_launch(void* const* d_in, const int* in_sizes, int n_in,
                              void* d_out, int out_size) {
    const float* x    = (const float*)d_in[0];
    const float* w5   = (const float*)d_in[1];
    const float* b5   = (const float*)d_in[2];
    const float* w10  = (const float*)d_in[3];
    const float* b10  = (const float*)d_in[4];
    const float* w15  = (const float*)d_in[5];
    const float* b15  = (const float*)d_in[6];
    const float* gw   = (const float*)d_in[7];
    const float* gb   = (const float*)d_in[8];
    const float* mw   = (const float*)d_in[9];
    const float* mb   = (const float*)d_in[10];
    const float* gamma= (const float*)d_in[11];
    const float* beta = (const float*)d_in[12];
    float* out = (float*)d_out;

    const int smem1 = SMEM1_U32 * 4;
    const int smem2 = SMEM2_U32 * 4;
    cudaFuncSetAttribute(k_conv1, cudaFuncAttributeMaxDynamicSharedMemorySize, smem1);
    cudaFuncSetAttribute(k_conv2, cudaFuncAttributeMaxDynamicSharedMemorySize, smem2);

    k_pool5   <<<(921600 + 255) / 256, 256>>>(x);
    k_poolrest<<<(332800 + 255) / 256, 256>>>();
    k_prepw   <<<32, 256>>>(w5, w10, w15, gw, mw);

    dim3 grid1(GX, GY1, 32);
    dim3 grid2(GX, GY2, 32);
    k_conv1<<<grid1, 256, smem1>>>(x, b5, b10, b15);
    k_conv2<<<grid2, 256, smem2>>>(gb, mb, out);

    k_stats<<<1, 512>>>(gamma, beta);
    k_norm <<<(5760000 + 255) / 256, 256>>>(out);
}

// round 16
// speedup vs baseline: 1.0508x; 1.0508x over previous
#include <cuda_runtime.h>
#include <cuda_bf16.h>
#include <cstdint>

typedef unsigned int u32;

#define HH 300
#define WW 300
#define TW 32
#define GX 10

// ---- conv1 tile: 32 x 8 ----
#define TH1 8
#define INH1 10
#define XP 344                 // x-tile channel-pair stride (344%32==24 -> conflict-free)
#define GY1 38
// us array widths (pooled cols + 1 zero slot)
#define W5 9
#define W10 6
#define W15 5
// smem u32 offsets (conv1)
#define XH_OFF 0
#define XL_OFF (4*XP)                    // 1376
#define US5H_OFF (2*4*XP)                // 2752
#define US5L_OFF (US5H_OFF + 4*10*W5)    // +360
#define US10H_OFF (US5L_OFF + 4*10*W5)
#define US10L_OFF (US10H_OFF + 4*10*W10)
#define US15H_OFF (US10L_OFF + 4*10*W10)
#define US15L_OFF (US15H_OFF + 4*10*W15)
#define BSM1_OFF (US15L_OFF + 4*10*W15)  // 4352
#define NFRAG1 27
#define BIAS1_OFF (BSM1_OFF + NFRAG1*128)
#define SMEM1_U32 (BIAS1_OFF + 32)

// ---- conv2 tile: 32 x 16 ----
#define TH2 16
#define INH2 18
#define RS2 35                 // row stride (35%32==3, coprime -> conflict-free A loads)
#define CS2 (INH2*RS2)         // 630
#define GY2 19
#define NBLK (GX*GY2*32)       // 6080
#define K2 224
#define K2R 216
#define STEPS2 14
#define NT2 2
#define BSM2_OFF (24*CS2)                 // 15120
#define KOFF_OFF (BSM2_OFF + STEPS2*NT2*2*32*2)
#define BIAS2_OFF (KOFF_OFF + K2)
#define RED2_OFF (BIAS2_OFF + 16)
#define SMEM2_U32 (RED2_OFF + 128 + 8)

// ---------------- device scratch ----------------
__device__ u32   g_pk[32u*24u*HH*WW];
__device__ float p5f[32*8*60*60];
__device__ float p10f[32*8*30*30];
__device__ float p15f[32*8*20*20];
__device__ u32   bfrag1[NFRAG1*128];
__device__ u32   bfrag2[STEPS2*NT2*2*32*2];
__device__ float part_buf[16*NBLK];   // TRANSPOSED: [v][blin] for coalesced stats
__device__ float bn_buf[16];

// ---------------- helpers ----------------
__device__ __forceinline__ u32 pack_split(float v) {
    __nv_bfloat16 h = __float2bfloat16(v);
    float hf = __bfloat162float(h);
    __nv_bfloat16 l = __float2bfloat16(v - hf);
    return ((u32)__bfloat16_as_ushort(h) << 16) | (u32)__bfloat16_as_ushort(l);
}
__device__ __forceinline__ void mma_bf16(float* d, u32 a0, u32 a1, u32 a2, u32 a3,
                                         u32 b0, u32 b1) {
    asm volatile(
        "mma.sync.aligned.m16n8k16.row.col.f32.bf16.bf16.f32 "
        "{%0,%1,%2,%3},{%4,%5,%6,%7},{%8,%9},{%0,%1,%2,%3};"
        : "+f"(d[0]), "+f"(d[1]), "+f"(d[2]), "+f"(d[3])
        : "r"(a0), "r"(a1), "r"(a2), "r"(a3), "r"(b0), "r"(b1));
}
// truncation split of (v0,v1) into hi word + rounded-lo word
__device__ __forceinline__ void split2(float v0, float v1, u32& H, u32& L) {
    u32 u0 = __float_as_uint(v0), u1 = __float_as_uint(v1);
    H = __byte_perm(u0, u1, 0x7632);
    float h0 = __uint_as_float(u0 & 0xFFFF0000u);
    float h1 = __uint_as_float(u1 & 0xFFFF0000u);
    __nv_bfloat162 Ll = __floats2bfloat162_rn(v0 - h0, v1 - h1);
    L = *reinterpret_cast<u32*>(&Ll);
}

// ---------------- pools (fp32) ----------------
__global__ void k_pool5(const float* __restrict__ x) {
    int i = blockIdx.x * blockDim.x + threadIdx.x;
    if (i >= 32*8*60*60) return;
    int px = i % 60; int t = i / 60;
    int py = t % 60; t /= 60;
    int c  = t % 8;  int b = t / 8;
    const float* base = x + ((size_t)(b*8 + c)*HH + py*5)*WW + px*5;
    float s = 0.f;
    #pragma unroll
    for (int r = 0; r < 5; r++)
        #pragma unroll
        for (int q = 0; q < 5; q++) s += base[r*WW + q];
    p5f[i] = s * (1.0f/25.0f);
}
__global__ void k_poolrest() {
    int i = blockIdx.x * blockDim.x + threadIdx.x;
    if (i < 32*8*30*30) {
        int px = i % 30; int t = i / 30;
        int py = t % 30; t /= 30;
        int c  = t % 8;  int b = t / 8;
        const float* base = p5f + ((b*8 + c)*60 + py*2)*60 + px*2;
        p10f[i] = (base[0] + base[1] + base[60] + base[61]) * 0.25f;
    }
    int j = i - 32*8*30*30;
    if (j >= 0 && j < 32*8*20*20) {
        int px = j % 20; int t = j / 20;
        int py = t % 20; t /= 20;
        int c  = t % 8;  int b = t / 8;
        const float* base = p5f + ((b*8 + c)*60 + py*3)*60 + px*3;
        float s = 0.f;
        #pragma unroll
        for (int r = 0; r < 3; r++)
            #pragma unroll
            for (int q = 0; q < 3; q++) s += base[r*60 + q];
        p15f[j] = s * (1.0f/9.0f);
    }
}

// ---------------- weight fragment prep ----------------
__global__ void k_prepw(const float* __restrict__ w5,  const float* __restrict__ w10,
                        const float* __restrict__ w15, const float* __restrict__ gw,
                        const float* __restrict__ mw) {
    int tid = blockIdx.x * blockDim.x + threadIdx.x;
    for (int e = tid; e < NFRAG1*128; e += blockDim.x * gridDim.x) {
        int blk = e >> 7;
        int rem = e & 127;
        int sp = rem >> 6;
        int lane = (rem & 63) >> 1;
        int r = rem & 1;
        int br = blk / 9, tap = blk % 9;
        const float* w = (br == 0) ? w5 : (br == 1 ? w10 : w15);
        int n = lane >> 2;
        int k0 = (lane & 3)*2 + r*8;
        float v0 = w[(n*16 + k0    )*9 + tap];
        float v1 = w[(n*16 + k0 + 1)*9 + tap];
        u32 word;
        if (sp == 0) {
            word = ((u32)__bfloat16_as_ushort(__float2bfloat16(v1)) << 16)
                 |  (u32)__bfloat16_as_ushort(__float2bfloat16(v0));
        } else {
            float h0 = __bfloat162float(__float2bfloat16(v0));
            float h1 = __bfloat162float(__float2bfloat16(v1));
            word = ((u32)__bfloat16_as_ushort(__float2bfloat16(v1 - h1)) << 16)
                 |  (u32)__bfloat16_as_ushort(__float2bfloat16(v0 - h0));
        }
        bfrag1[e] = word;
    }
    for (int e = tid; e < STEPS2*NT2*2*32*2; e += blockDim.x * gridDim.x) {
        int r = e & 1; int t = (e >> 1) & 31; int sp = (e >> 6) & 1;
        int nt = (e >> 7) % NT2; int step = (e >> 7) / NT2;
        int n = nt*8 + t/4;
        int k0 = step*16 + (t & 3)*2 + r*8;
        float v0 = 0.f, v1 = 0.f;
        if (k0 < K2R)
            v0 = (n < 8) ? gw[(n*24 + k0/9)*9 + k0%9] : mw[((n-8)*24 + k0/9)*9 + k0%9];
        int k1 = k0 + 1;
        if (k1 < K2R)
            v1 = (n < 8) ? gw[(n*24 + k1/9)*9 + k1%9] : mw[((n-8)*24 + k1/9)*9 + k1%9];
        u32 w;
        if (sp == 0) {
            w = ((u32)__bfloat16_as_ushort(__float2bfloat16(v1)) << 16)
              |  (u32)__bfloat16_as_ushort(__float2bfloat16(v0));
        } else {
            float h0 = __bfloat162float(__float2bfloat16(v0));
            float h1 = __bfloat162float(__float2bfloat16(v1));
            w = ((u32)__bfloat16_as_ushort(__float2bfloat16(v1 - h1)) << 16)
              |  (u32)__bfloat16_as_ushort(__float2bfloat16(v0 - h0));
        }
        bfrag2[e] = w;
    }
}

// ---------------- conv1: branch GEMMs, pooled-col up arrays (R14 winner) ----------------
__global__ void __launch_bounds__(256, 3)
k_conv1(const float* __restrict__ x,
        const float* __restrict__ b5, const float* __restrict__ b10,
        const float* __restrict__ b15) {
    extern __shared__ u32 smu[];
    float* bias = (float*)(smu + BIAS1_OFF);

    int tid = threadIdx.x;
    int b  = blockIdx.z;
    int x0 = blockIdx.x * TW, y0 = blockIdx.y * TH1;

    int xm = (x0 > 1) ? (x0 - 1) : 0;
    int pc05 = xm/5, pc010 = xm/10, pc015 = xm/15;

    // x channels: 4 c2-pairs x 340 pixels
    for (int i = tid; i < 4*340; i += 256) {
        int c2 = i / 340, pix = i - c2*340;
        int ty = pix / 34, tx = pix - ty*34;
        int gy = y0 - 1 + ty, gx = x0 - 1 + tx;
        float v0 = 0.f, v1 = 0.f;
        if ((unsigned)gy < HH && (unsigned)gx < WW) {
            const float* p = x + ((size_t)(b*8 + 2*c2)*HH + gy)*WW + gx;
            v0 = p[0]; v1 = p[(size_t)HH*WW];
        }
        u32 H, L; split2(v0, v1, H, L);
        smu[XH_OFF + c2*XP + pix] = H;
        smu[XL_OFF + c2*XP + pix] = L;
    }
    // pooled-col up arrays: 800 elements total
    for (int e = tid; e < 800; e += 256) {
        float v0 = 0.f, v1 = 0.f;
        int hoff, loff, idx;
        if (e < 360) {                       // us5: [c2][10][9]
            int c2 = e / 90, rm = e - c2*90;
            int ty = rm / W5, pc = rm - ty*W5;
            int gy = y0 - 1 + ty, pcg = pc05 + pc;
            if ((unsigned)gy < HH && pc < 8 && pcg < 60) {
                const float* p = p5f + ((b*8 + 2*c2)*60 + gy/5)*60 + pcg;
                v0 = p[0]; v1 = p[3600];
            }
            hoff = US5H_OFF; loff = US5L_OFF; idx = e;
        } else if (e < 600) {                // us10: [c2][10][6]
            int e2 = e - 360;
            int c2 = e2 / 60, rm = e2 - c2*60;
            int ty = rm / W10, pc = rm - ty*W10;
            int gy = y0 - 1 + ty, pcg = pc010 + pc;
            if ((unsigned)gy < HH && pc < 5 && pcg < 30) {
                const float* p = p10f + ((b*8 + 2*c2)*30 + gy/10)*30 + pcg;
                v0 = p[0]; v1 = p[900];
            }
            hoff = US10H_OFF; loff = US10L_OFF; idx = e2;
        } else {                             // us15: [c2][10][5]
            int e3 = e - 600;
            int c2 = e3 / 50, rm = e3 - c2*50;
            int ty = rm / W15, pc = rm - ty*W15;
            int gy = y0 - 1 + ty, pcg = pc015 + pc;
            if ((unsigned)gy < HH && pc < 4 && pcg < 20) {
                const float* p = p15f + ((b*8 + 2*c2)*20 + gy/15)*20 + pcg;
                v0 = p[0]; v1 = p[400];
            }
            hoff = US15H_OFF; loff = US15L_OFF; idx = e3;
        }
        u32 H, L; split2(v0, v1, H, L);
        smu[hoff + idx] = H;
        smu[loff + idx] = L;
    }
    for (int i = tid; i < NFRAG1*128; i += 256) smu[BSM1_OFF + i] = bfrag1[i];
    if (tid < 24)
        bias[tid] = (tid < 8) ? b5[tid] : (tid < 16 ? b10[tid-8] : b15[tid-16]);
    __syncthreads();

    int lane = tid & 31, w = tid >> 5;
    int g = lane >> 2, tg = lane & 3;
    int s = w >> 2, wr = w & 3;
    int ry0 = wr*2;

    // per-lane packed pooled cols (byte q = tap col q), zero slot when invalid
    int gxa = x0 - 1 + s*16 + g;
    u32 pA[3] = {0,0,0}, pB[3] = {0,0,0};
    #pragma unroll
    for (int q = 0; q < 3; q++) {
        int xa = gxa + q, xb = xa + 8;
        u32 a5  = ((unsigned)xa < WW) ? (u32)(xa/5  - pc05)  : 8u;
        u32 b5_ = ((unsigned)xb < WW) ? (u32)(xb/5  - pc05)  : 8u;
        u32 a10 = ((unsigned)xa < WW) ? (u32)(xa/10 - pc010) : 5u;
        u32 b10_= ((unsigned)xb < WW) ? (u32)(xb/10 - pc010) : 5u;
        u32 a15 = ((unsigned)xa < WW) ? (u32)(xa/15 - pc015) : 4u;
        u32 b15_= ((unsigned)xb < WW) ? (u32)(xb/15 - pc015) : 4u;
        pA[0] |= a5  << (q*8); pB[0] |= b5_  << (q*8);
        pA[1] |= a10 << (q*8); pB[1] |= b10_ << (q*8);
        pA[2] |= a15 << (q*8); pB[2] |= b15_ << (q*8);
    }

    const int USW[3]  = {W5, W10, W15};
    const int USH[3]  = {US5H_OFF, US10H_OFF, US15H_OFF};
    const int USL[3]  = {US5L_OFF, US10L_OFF, US15L_OFF};

    float d[2][3][4];
    #pragma unroll
    for (int j = 0; j < 2; j++)
        #pragma unroll
        for (int br = 0; br < 3; br++)
            #pragma unroll
            for (int q = 0; q < 4; q++) d[j][br][q] = 0.f;

    #pragma unroll
    for (int tapr = 0; tapr < 3; tapr++) {
        #pragma unroll
        for (int tapc = 0; tapc < 3; tapc++) {
            int tap = tapr*3 + tapc;
            uint2 bh[3], bl[3];
            #pragma unroll
            for (int br = 0; br < 3; br++) {
                int bb = BSM1_OFF + (br*9 + tap)*128 + lane*2;
                bh[br] = *reinterpret_cast<const uint2*>(&smu[bb]);
                bl[br] = *reinterpret_cast<const uint2*>(&smu[bb + 64]);
            }
            #pragma unroll
            for (int j = 0; j < 2; j++) {
                int ty = ry0 + j + tapr;
                int xi = tg*XP + ty*34 + s*16 + g + tapc;
                u32 xh0 = smu[XH_OFF + xi], xh1 = smu[XH_OFF + xi + 8];
                u32 xl0 = smu[XL_OFF + xi], xl1 = smu[XL_OFF + xi + 8];
                #pragma unroll
                for (int br = 0; br < 3; br++) {
                    int pa = (pA[br] >> (tapc*8)) & 0xFF;
                    int pb = (pB[br] >> (tapc*8)) & 0xFF;
                    int ub = (tg*10 + ty)*USW[br];
                    u32 uh0 = smu[USH[br] + ub + pa];
                    u32 uh1 = smu[USH[br] + ub + pb];
                    u32 ul0 = smu[USL[br] + ub + pa];
                    u32 ul1 = smu[USL[br] + ub + pb];
                    mma_bf16(d[j][br], xh0, xh1, uh0, uh1, bh[br].x, bh[br].y);
                    mma_bf16(d[j][br], xh0, xh1, uh0, uh1, bl[br].x, bl[br].y);
                    mma_bf16(d[j][br], xl0, xl1, ul0, ul1, bh[br].x, bh[br].y);
                }
            }
        }
    }

    // epilogue: +bias, split-pack, store to g_pk
    #pragma unroll
    for (int j = 0; j < 2; j++) {
        int py = y0 + ry0 + j;
        if (py >= HH) continue;
        int px0 = x0 + s*16 + g;
        #pragma unroll
        for (int br = 0; br < 3; br++) {
            int oc = br*8 + 2*tg;
            float bv0 = bias[oc], bv1 = bias[oc+1];
            size_t r0 = ((size_t)(b*24 + oc  )*HH + py)*WW;
            size_t r1 = ((size_t)(b*24 + oc+1)*HH + py)*WW;
            if (px0 < WW) {
                g_pk[r0 + px0] = pack_split(d[j][br][0] + bv0);
                g_pk[r1 + px0] = pack_split(d[j][br][1] + bv1);
            }
            if (px0 + 8 < WW) {
                g_pk[r0 + px0+8] = pack_split(d[j][br][2] + bv0);
                g_pk[r1 + px0+8] = pack_split(d[j][br][3] + bv1);
            }
        }
    }
}

// ---------------- conv2: gated pair + BN partials ----------------
// element-wise COALESCED loader + padded smem strides (RS2=35)
__global__ void __launch_bounds__(256, 2)
k_conv2(const float* __restrict__ gb, const float* __restrict__ mb,
        float* __restrict__ out) {
    extern __shared__ u32 smu[];
    u32* tile = smu;
    u32* bsm  = smu + BSM2_OFF;
    int* koffs = (int*)(smu + KOFF_OFF);
    float* bias = (float*)(smu + BIAS2_OFF);
    float* red  = (float*)(smu + RED2_OFF);

    int tid = threadIdx.x;
    int b  = blockIdx.z;
    int x0 = blockIdx.x * TW, y0 = blockIdx.y * TH2;

    // element-wise coalesced tile load (consecutive tid -> consecutive gx)
    for (int i = tid; i < 24*18*34; i += 256) {
        int tx = i % 34; int t = i / 34;
        int ty = t % 18; int c = t / 18;
        int gy = y0 - 1 + ty, gx = x0 - 1 + tx;
        u32 v = 0u;
        if ((unsigned)gy < HH && (unsigned)gx < WW)
            v = g_pk[((size_t)(b*24 + c)*HH + gy)*WW + gx];
        tile[c*CS2 + ty*RS2 + tx] = v;
    }
    for (int i = tid; i < STEPS2*NT2*2*32*2; i += 256) bsm[i] = bfrag2[i];
    for (int k = tid; k < K2; k += 256)
        koffs[k] = (k < K2R) ? (k/9)*CS2 + ((k%9)/3)*RS2 + (k%3) : 0;
    if (tid < 16) bias[tid] = (tid < 8) ? gb[tid] : mb[tid-8];
    __syncthreads();

    int lane = tid & 31, w = tid >> 5;
    int g = lane >> 2, tg = lane & 3;
    int s = w >> 2, wr = w & 3;

    float s0 = 0.f, s1 = 0.f, q0 = 0.f, q1 = 0.f;

    for (int p = 0; p < 2; p++) {
        int ry0 = wr*4 + p*2;
        int baseA = ry0*RS2 + s*16 + g;
        float d[2][NT2][4];
        #pragma unroll
        for (int j = 0; j < 2; j++)
            #pragma unroll
            for (int nt = 0; nt < NT2; nt++)
                #pragma unroll
                for (int q = 0; q < 4; q++) d[j][nt][q] = 0.f;

        for (int step = 0; step < STEPS2; step++) {
            int kb = step*16 + 2*tg;
            int o0 = koffs[kb], o1 = koffs[kb+1], o2 = koffs[kb+8], o3 = koffs[kb+9];
            u32 ah[2][4], al[2][4];
            #pragma unroll
            for (int j = 0; j < 2; j++) {
                int ba = baseA + j*RS2;
                u32 e00 = tile[ba + o0],   e01 = tile[ba + o1];
                u32 e02 = tile[ba + o2],   e03 = tile[ba + o3];
                u32 e10 = tile[ba+8 + o0], e11 = tile[ba+8 + o1];
                u32 e12 = tile[ba+8 + o2], e13 = tile[ba+8 + o3];
                ah[j][0] = __byte_perm(e00, e01, 0x7632);
                ah[j][1] = __byte_perm(e10, e11, 0x7632);
                ah[j][2] = __byte_perm(e02, e03, 0x7632);
                ah[j][3] = __byte_perm(e12, e13, 0x7632);
                al[j][0] = __byte_perm(e00, e01, 0x5410);
                al[j][1] = __byte_perm(e10, e11, 0x5410);
                al[j][2] = __byte_perm(e02, e03, 0x5410);
                al[j][3] = __byte_perm(e12, e13, 0x5410);
            }
            #pragma unroll
            for (int nt = 0; nt < NT2; nt++) {
                int bi = ((step*NT2 + nt)*2)*64 + lane*2;
                uint2 bh = *reinterpret_cast<const uint2*>(&bsm[bi]);
                uint2 bl = *reinterpret_cast<const uint2*>(&bsm[bi + 64]);
                #pragma unroll
                for (int j = 0; j < 2; j++) {
                    mma_bf16(d[j][nt], ah[j][0], ah[j][1], ah[j][2], ah[j][3], bh.x, bh.y);
                    mma_bf16(d[j][nt], ah[j][0], ah[j][1], ah[j][2], ah[j][3], bl.x, bl.y);
                    mma_bf16(d[j][nt], al[j][0], al[j][1], al[j][2], al[j][3], bh.x, bh.y);
                }
            }
        }

        int oc0 = 2*tg;
        float bg0 = bias[oc0], bg1 = bias[oc0+1];
        float bm0 = bias[8+oc0], bm1 = bias[8+oc0+1];
        #pragma unroll
        for (int j = 0; j < 2; j++) {
            int py = y0 + ry0 + j;
            bool vy = (py < HH);
            int px0 = x0 + s*16 + g;
            size_t r0 = ((size_t)(b*8 + oc0  )*HH + py)*WW;
            size_t r1 = ((size_t)(b*8 + oc0+1)*HH + py)*WW;
            #pragma unroll
            for (int h = 0; h < 2; h++) {
                int px = px0 + h*8;
                bool vld = vy && (px < WW);
                float ga = d[j][0][2*h]   + bg0;
                float gb_ = d[j][0][2*h+1] + bg1;
                float ma = d[j][1][2*h]   + bm0;
                float mb_ = d[j][1][2*h+1] + bm1;
                float y0v = ga / (1.f + __expf(-ma));
                float y1v = gb_ / (1.f + __expf(-mb_));
                if (vld) {
                    out[r0 + px] = y0v;
                    out[r1 + px] = y1v;
                    s0 += y0v; q0 += y0v*y0v;
                    s1 += y1v; q1 += y1v*y1v;
                }
            }
        }
    }

    #pragma unroll
    for (int dlt = 4; dlt < 32; dlt <<= 1) {
        s0 += __shfl_xor_sync(0xffffffffu, s0, dlt);
        s1 += __shfl_xor_sync(0xffffffffu, s1, dlt);
        q0 += __shfl_xor_sync(0xffffffffu, q0, dlt);
        q1 += __shfl_xor_sync(0xffffffffu, q1, dlt);
    }
    if (g == 0) {
        red[w*16 + 2*tg]     = s0;
        red[w*16 + 2*tg + 1] = s1;
        red[w*16 + 8 + 2*tg]     = q0;
        red[w*16 + 8 + 2*tg + 1] = q1;
    }
    __syncthreads();
    if (tid < 16) {
        float t = 0.f;
        #pragma unroll
        for (int w2 = 0; w2 < 8; w2++) t += red[w2*16 + tid];
        int blin = (b*GY2 + blockIdx.y)*GX + blockIdx.x;
        part_buf[tid*NBLK + blin] = t;   // transposed layout
    }
}

// ---------------- BN stats: 16 warps, coalesced, deterministic ----------------
__global__ void k_stats(const float* __restrict__ gamma, const float* __restrict__ beta) {
    __shared__ double sums[16];
    int tid = threadIdx.x;
    int w = tid >> 5, lane = tid & 31;
    double a0 = 0.0, a1 = 0.0, a2 = 0.0, a3 = 0.0;
    const float* src = part_buf + w*NBLK;
    for (int i = lane; i < NBLK; i += 128) {
        a0 += (double)src[i];
        if (i + 32 < NBLK) a1 += (double)src[i + 32];
        if (i + 64 < NBLK) a2 += (double)src[i + 64];
        if (i + 96 < NBLK) a3 += (double)src[i + 96];
    }
    double acc = (a0 + a1) + (a2 + a3);
    #pragma unroll
    for (int d = 16; d > 0; d >>= 1)
        acc += __shfl_xor_sync(0xffffffffu, acc, d);
    if (lane == 0) sums[w] = acc;
    __syncthreads();
    if (tid < 8) {
        const double N = 2880000.0;
        double mean = sums[tid] / N;
        double ex2  = sums[8 + tid] / N;
        double var  = ex2 - mean * mean;
        double scale = (double)gamma[tid] / sqrt(var + 1e-5);
        double shift = (double)beta[tid] - mean * scale;
        bn_buf[tid]     = (float)scale;
        bn_buf[8 + tid] = (float)shift;
    }
}

// ---------------- normalize ----------------
__global__ void k_norm(float* __restrict__ out) {
    int i = blockIdx.x * blockDim.x + threadIdx.x;
    if (i >= 5760000) return;
    int c = (i / 22500) & 7;
    float sc = bn_buf[c], sh = bn_buf[8 + c];
    float4 v = reinterpret_cast<float4*>(out)[i];
    v.x = v.x * sc + sh;
    v.y = v.y * sc + sh;
    v.z = v.z * sc + sh;
    v.w = v.w * sc + sh;
    reinterpret_cast<float4*>(out)[i] = v;
}

// ---------------- launch ----------------
extern "C" void kernel_launch(void* const* d_in, const int* in_sizes, int n_in,
                              void* d_out, int out_size) {
    const float* x    = (const float*)d_in[0];
    const float* w5   = (const float*)d_in[1];
    const float* b5   = (const float*)d_in[2];
    const float* w10  = (const float*)d_in[3];
    const float* b10  = (const float*)d_in[4];
    const float* w15  = (const float*)d_in[5];
    const float* b15  = (const float*)d_in[6];
    const float* gw   = (const float*)d_in[7];
    const float* gb   = (const float*)d_in[8];
    const float* mw   = (const float*)d_in[9];
    const float* mb   = (const float*)d_in[10];
    const float* gamma= (const float*)d_in[11];
    const float* beta = (const float*)d_in[12];
    float* out = (float*)d_out;

    const int smem1 = SMEM1_U32 * 4;
    const int smem2 = SMEM2_U32 * 4;
    cudaFuncSetAttribute(k_conv1, cudaFuncAttributeMaxDynamicSharedMemorySize, smem1);
    cudaFuncSetAttribute(k_conv2, cudaFuncAttributeMaxDynamicSharedMemorySize, smem2);

    k_pool5   <<<(921600 + 255) / 256, 256>>>(x);
    k_poolrest<<<(332800 + 255) / 256, 256>>>();
    k_prepw   <<<32, 256>>>(w5, w10, w15, gw, mw);

    dim3 grid1(GX, GY1, 32);
    dim3 grid2(GX, GY2, 32);
    k_conv1<<<grid1, 256, smem1>>>(x, b5, b10, b15);
    k_conv2<<<grid2, 256, smem2>>>(gb, mb, out);

    k_stats<<<1, 512>>>(gamma, beta);
    k_norm <<<(5760000 + 255) / 256, 256>>>(out);
}

// round 17
// speedup vs baseline: 1.0572x; 1.0061x over previous
#include <cuda_runtime.h>
#include <cuda_bf16.h>
#include <cstdint>

typedef unsigned int u32;

#define HH 300
#define WW 300
#define TW 32
#define GX 10

// ---- conv1 tile: 32 x 8 ----
#define TH1 8
#define INH1 10
#define XP 344                 // x-tile channel-pair stride (344%32==24 -> conflict-free)
#define GY1 38
// us array widths (pooled cols + 1 zero slot)
#define W5 9
#define W10 6
#define W15 5
// smem u32 offsets (conv1)
#define XH_OFF 0
#define XL_OFF (4*XP)                    // 1376
#define US5H_OFF (2*4*XP)                // 2752
#define US5L_OFF (US5H_OFF + 4*10*W5)    // +360
#define US10H_OFF (US5L_OFF + 4*10*W5)
#define US10L_OFF (US10H_OFF + 4*10*W10)
#define US15H_OFF (US10L_OFF + 4*10*W10)
#define US15L_OFF (US15H_OFF + 4*10*W15)
#define BSM1_OFF (US15L_OFF + 4*10*W15)  // 4352
#define NFRAG1 27
#define BIAS1_OFF (BSM1_OFF + NFRAG1*128)
#define SMEM1_U32 (BIAS1_OFF + 32)

// ---- conv2 tile: 32 x 16, b-frags via LDG (L1-resident) ----
#define TH2 16
#define INH2 18
#define RS2 35                 // row stride (35%32==3, coprime -> conflict-free A loads)
#define CS2 (INH2*RS2)         // 630
#define GY2 19
#define NBLK (GX*GY2*32)       // 6080
#define K2 224
#define K2R 216
#define STEPS2 14
#define NT2 2
#define KOFF_OFF (24*CS2)                 // 15120
#define BIAS2_OFF (KOFF_OFF + K2)
#define RED2_OFF (BIAS2_OFF + 16)
#define SMEM2_U32 (RED2_OFF + 128 + 8)    // ~60.6 KB -> 3 blocks/SM

// ---------------- device scratch ----------------
__device__ u32   g_pk[32u*24u*HH*WW];
__device__ float p5f[32*8*60*60];
__device__ float p10f[32*8*30*30];
__device__ float p15f[32*8*20*20];
__device__ u32   bfrag1[NFRAG1*128];
__device__ u32   bfrag2[STEPS2*NT2*2*32*2];
__device__ float part_buf[16*NBLK];   // TRANSPOSED: [v][blin] for coalesced stats
__device__ float bn_buf[16];

// ---------------- helpers ----------------
__device__ __forceinline__ u32 pack_split(float v) {
    __nv_bfloat16 h = __float2bfloat16(v);
    float hf = __bfloat162float(h);
    __nv_bfloat16 l = __float2bfloat16(v - hf);
    return ((u32)__bfloat16_as_ushort(h) << 16) | (u32)__bfloat16_as_ushort(l);
}
__device__ __forceinline__ void mma_bf16(float* d, u32 a0, u32 a1, u32 a2, u32 a3,
                                         u32 b0, u32 b1) {
    asm volatile(
        "mma.sync.aligned.m16n8k16.row.col.f32.bf16.bf16.f32 "
        "{%0,%1,%2,%3},{%4,%5,%6,%7},{%8,%9},{%0,%1,%2,%3};"
        : "+f"(d[0]), "+f"(d[1]), "+f"(d[2]), "+f"(d[3])
        : "r"(a0), "r"(a1), "r"(a2), "r"(a3), "r"(b0), "r"(b1));
}
// truncation split of (v0,v1) into hi word + rounded-lo word
__device__ __forceinline__ void split2(float v0, float v1, u32& H, u32& L) {
    u32 u0 = __float_as_uint(v0), u1 = __float_as_uint(v1);
    H = __byte_perm(u0, u1, 0x7632);
    float h0 = __uint_as_float(u0 & 0xFFFF0000u);
    float h1 = __uint_as_float(u1 & 0xFFFF0000u);
    __nv_bfloat162 Ll = __floats2bfloat162_rn(v0 - h0, v1 - h1);
    L = *reinterpret_cast<u32*>(&Ll);
}

// ---------------- pools (fp32) ----------------
__global__ void k_pool5(const float* __restrict__ x) {
    int i = blockIdx.x * blockDim.x + threadIdx.x;
    if (i >= 32*8*60*60) return;
    int px = i % 60; int t = i / 60;
    int py = t % 60; t /= 60;
    int c  = t % 8;  int b = t / 8;
    const float* base = x + ((size_t)(b*8 + c)*HH + py*5)*WW + px*5;
    float s = 0.f;
    #pragma unroll
    for (int r = 0; r < 5; r++)
        #pragma unroll
        for (int q = 0; q < 5; q++) s += base[r*WW + q];
    p5f[i] = s * (1.0f/25.0f);
}
__global__ void k_poolrest() {
    int i = blockIdx.x * blockDim.x + threadIdx.x;
    if (i < 32*8*30*30) {
        int px = i % 30; int t = i / 30;
        int py = t % 30; t /= 30;
        int c  = t % 8;  int b = t / 8;
        const float* base = p5f + ((b*8 + c)*60 + py*2)*60 + px*2;
        p10f[i] = (base[0] + base[1] + base[60] + base[61]) * 0.25f;
    }
    int j = i - 32*8*30*30;
    if (j >= 0 && j < 32*8*20*20) {
        int px = j % 20; int t = j / 20;
        int py = t % 20; t /= 20;
        int c  = t % 8;  int b = t / 8;
        const float* base = p5f + ((b*8 + c)*60 + py*3)*60 + px*3;
        float s = 0.f;
        #pragma unroll
        for (int r = 0; r < 3; r++)
            #pragma unroll
            for (int q = 0; q < 3; q++) s += base[r*60 + q];
        p15f[j] = s * (1.0f/9.0f);
    }
}

// ---------------- weight fragment prep ----------------
__global__ void k_prepw(const float* __restrict__ w5,  const float* __restrict__ w10,
                        const float* __restrict__ w15, const float* __restrict__ gw,
                        const float* __restrict__ mw) {
    int tid = blockIdx.x * blockDim.x + threadIdx.x;
    for (int e = tid; e < NFRAG1*128; e += blockDim.x * gridDim.x) {
        int blk = e >> 7;
        int rem = e & 127;
        int sp = rem >> 6;
        int lane = (rem & 63) >> 1;
        int r = rem & 1;
        int br = blk / 9, tap = blk % 9;
        const float* w = (br == 0) ? w5 : (br == 1 ? w10 : w15);
        int n = lane >> 2;
        int k0 = (lane & 3)*2 + r*8;
        float v0 = w[(n*16 + k0    )*9 + tap];
        float v1 = w[(n*16 + k0 + 1)*9 + tap];
        u32 word;
        if (sp == 0) {
            word = ((u32)__bfloat16_as_ushort(__float2bfloat16(v1)) << 16)
                 |  (u32)__bfloat16_as_ushort(__float2bfloat16(v0));
        } else {
            float h0 = __bfloat162float(__float2bfloat16(v0));
            float h1 = __bfloat162float(__float2bfloat16(v1));
            word = ((u32)__bfloat16_as_ushort(__float2bfloat16(v1 - h1)) << 16)
                 |  (u32)__bfloat16_as_ushort(__float2bfloat16(v0 - h0));
        }
        bfrag1[e] = word;
    }
    for (int e = tid; e < STEPS2*NT2*2*32*2; e += blockDim.x * gridDim.x) {
        int r = e & 1; int t = (e >> 1) & 31; int sp = (e >> 6) & 1;
        int nt = (e >> 7) % NT2; int step = (e >> 7) / NT2;
        int n = nt*8 + t/4;
        int k0 = step*16 + (t & 3)*2 + r*8;
        float v0 = 0.f, v1 = 0.f;
        if (k0 < K2R)
            v0 = (n < 8) ? gw[(n*24 + k0/9)*9 + k0%9] : mw[((n-8)*24 + k0/9)*9 + k0%9];
        int k1 = k0 + 1;
        if (k1 < K2R)
            v1 = (n < 8) ? gw[(n*24 + k1/9)*9 + k1%9] : mw[((n-8)*24 + k1/9)*9 + k1%9];
        u32 w;
        if (sp == 0) {
            w = ((u32)__bfloat16_as_ushort(__float2bfloat16(v1)) << 16)
              |  (u32)__bfloat16_as_ushort(__float2bfloat16(v0));
        } else {
            float h0 = __bfloat162float(__float2bfloat16(v0));
            float h1 = __bfloat162float(__float2bfloat16(v1));
            w = ((u32)__bfloat16_as_ushort(__float2bfloat16(v1 - h1)) << 16)
              |  (u32)__bfloat16_as_ushort(__float2bfloat16(v0 - h0));
        }
        bfrag2[e] = w;
    }
}

// ---------------- conv1: branch GEMMs, pooled-col up arrays (R14 winner, untouched) ----------------
__global__ void __launch_bounds__(256, 3)
k_conv1(const float* __restrict__ x,
        const float* __restrict__ b5, const float* __restrict__ b10,
        const float* __restrict__ b15) {
    extern __shared__ u32 smu[];
    float* bias = (float*)(smu + BIAS1_OFF);

    int tid = threadIdx.x;
    int b  = blockIdx.z;
    int x0 = blockIdx.x * TW, y0 = blockIdx.y * TH1;

    int xm = (x0 > 1) ? (x0 - 1) : 0;
    int pc05 = xm/5, pc010 = xm/10, pc015 = xm/15;

    // x channels: 4 c2-pairs x 340 pixels
    for (int i = tid; i < 4*340; i += 256) {
        int c2 = i / 340, pix = i - c2*340;
        int ty = pix / 34, tx = pix - ty*34;
        int gy = y0 - 1 + ty, gx = x0 - 1 + tx;
        float v0 = 0.f, v1 = 0.f;
        if ((unsigned)gy < HH && (unsigned)gx < WW) {
            const float* p = x + ((size_t)(b*8 + 2*c2)*HH + gy)*WW + gx;
            v0 = p[0]; v1 = p[(size_t)HH*WW];
        }
        u32 H, L; split2(v0, v1, H, L);
        smu[XH_OFF + c2*XP + pix] = H;
        smu[XL_OFF + c2*XP + pix] = L;
    }
    // pooled-col up arrays: 800 elements total
    for (int e = tid; e < 800; e += 256) {
        float v0 = 0.f, v1 = 0.f;
        int hoff, loff, idx;
        if (e < 360) {                       // us5: [c2][10][9]
            int c2 = e / 90, rm = e - c2*90;
            int ty = rm / W5, pc = rm - ty*W5;
            int gy = y0 - 1 + ty, pcg = pc05 + pc;
            if ((unsigned)gy < HH && pc < 8 && pcg < 60) {
                const float* p = p5f + ((b*8 + 2*c2)*60 + gy/5)*60 + pcg;
                v0 = p[0]; v1 = p[3600];
            }
            hoff = US5H_OFF; loff = US5L_OFF; idx = e;
        } else if (e < 600) {                // us10: [c2][10][6]
            int e2 = e - 360;
            int c2 = e2 / 60, rm = e2 - c2*60;
            int ty = rm / W10, pc = rm - ty*W10;
            int gy = y0 - 1 + ty, pcg = pc010 + pc;
            if ((unsigned)gy < HH && pc < 5 && pcg < 30) {
                const float* p = p10f + ((b*8 + 2*c2)*30 + gy/10)*30 + pcg;
                v0 = p[0]; v1 = p[900];
            }
            hoff = US10H_OFF; loff = US10L_OFF; idx = e2;
        } else {                             // us15: [c2][10][5]
            int e3 = e - 600;
            int c2 = e3 / 50, rm = e3 - c2*50;
            int ty = rm / W15, pc = rm - ty*W15;
            int gy = y0 - 1 + ty, pcg = pc015 + pc;
            if ((unsigned)gy < HH && pc < 4 && pcg < 20) {
                const float* p = p15f + ((b*8 + 2*c2)*20 + gy/15)*20 + pcg;
                v0 = p[0]; v1 = p[400];
            }
            hoff = US15H_OFF; loff = US15L_OFF; idx = e3;
        }
        u32 H, L; split2(v0, v1, H, L);
        smu[hoff + idx] = H;
        smu[loff + idx] = L;
    }
    for (int i = tid; i < NFRAG1*128; i += 256) smu[BSM1_OFF + i] = bfrag1[i];
    if (tid < 24)
        bias[tid] = (tid < 8) ? b5[tid] : (tid < 16 ? b10[tid-8] : b15[tid-16]);
    __syncthreads();

    int lane = tid & 31, w = tid >> 5;
    int g = lane >> 2, tg = lane & 3;
    int s = w >> 2, wr = w & 3;
    int ry0 = wr*2;

    // per-lane packed pooled cols (byte q = tap col q), zero slot when invalid
    int gxa = x0 - 1 + s*16 + g;
    u32 pA[3] = {0,0,0}, pB[3] = {0,0,0};
    #pragma unroll
    for (int q = 0; q < 3; q++) {
        int xa = gxa + q, xb = xa + 8;
        u32 a5  = ((unsigned)xa < WW) ? (u32)(xa/5  - pc05)  : 8u;
        u32 b5_ = ((unsigned)xb < WW) ? (u32)(xb/5  - pc05)  : 8u;
        u32 a10 = ((unsigned)xa < WW) ? (u32)(xa/10 - pc010) : 5u;
        u32 b10_= ((unsigned)xb < WW) ? (u32)(xb/10 - pc010) : 5u;
        u32 a15 = ((unsigned)xa < WW) ? (u32)(xa/15 - pc015) : 4u;
        u32 b15_= ((unsigned)xb < WW) ? (u32)(xb/15 - pc015) : 4u;
        pA[0] |= a5  << (q*8); pB[0] |= b5_  << (q*8);
        pA[1] |= a10 << (q*8); pB[1] |= b10_ << (q*8);
        pA[2] |= a15 << (q*8); pB[2] |= b15_ << (q*8);
    }

    const int USW[3]  = {W5, W10, W15};
    const int USH[3]  = {US5H_OFF, US10H_OFF, US15H_OFF};
    const int USL[3]  = {US5L_OFF, US10L_OFF, US15L_OFF};

    float d[2][3][4];
    #pragma unroll
    for (int j = 0; j < 2; j++)
        #pragma unroll
        for (int br = 0; br < 3; br++)
            #pragma unroll
            for (int q = 0; q < 4; q++) d[j][br][q] = 0.f;

    #pragma unroll
    for (int tapr = 0; tapr < 3; tapr++) {
        #pragma unroll
        for (int tapc = 0; tapc < 3; tapc++) {
            int tap = tapr*3 + tapc;
            uint2 bh[3], bl[3];
            #pragma unroll
            for (int br = 0; br < 3; br++) {
                int bb = BSM1_OFF + (br*9 + tap)*128 + lane*2;
                bh[br] = *reinterpret_cast<const uint2*>(&smu[bb]);
                bl[br] = *reinterpret_cast<const uint2*>(&smu[bb + 64]);
            }
            #pragma unroll
            for (int j = 0; j < 2; j++) {
                int ty = ry0 + j + tapr;
                int xi = tg*XP + ty*34 + s*16 + g + tapc;
                u32 xh0 = smu[XH_OFF + xi], xh1 = smu[XH_OFF + xi + 8];
                u32 xl0 = smu[XL_OFF + xi], xl1 = smu[XL_OFF + xi + 8];
                #pragma unroll
                for (int br = 0; br < 3; br++) {
                    int pa = (pA[br] >> (tapc*8)) & 0xFF;
                    int pb = (pB[br] >> (tapc*8)) & 0xFF;
                    int ub = (tg*10 + ty)*USW[br];
                    u32 uh0 = smu[USH[br] + ub + pa];
                    u32 uh1 = smu[USH[br] + ub + pb];
                    u32 ul0 = smu[USL[br] + ub + pa];
                    u32 ul1 = smu[USL[br] + ub + pb];
                    mma_bf16(d[j][br], xh0, xh1, uh0, uh1, bh[br].x, bh[br].y);
                    mma_bf16(d[j][br], xh0, xh1, uh0, uh1, bl[br].x, bl[br].y);
                    mma_bf16(d[j][br], xl0, xl1, ul0, ul1, bh[br].x, bh[br].y);
                }
            }
        }
    }

    // epilogue: +bias, split-pack, store to g_pk
    #pragma unroll
    for (int j = 0; j < 2; j++) {
        int py = y0 + ry0 + j;
        if (py >= HH) continue;
        int px0 = x0 + s*16 + g;
        #pragma unroll
        for (int br = 0; br < 3; br++) {
            int oc = br*8 + 2*tg;
            float bv0 = bias[oc], bv1 = bias[oc+1];
            size_t r0 = ((size_t)(b*24 + oc  )*HH + py)*WW;
            size_t r1 = ((size_t)(b*24 + oc+1)*HH + py)*WW;
            if (px0 < WW) {
                g_pk[r0 + px0] = pack_split(d[j][br][0] + bv0);
                g_pk[r1 + px0] = pack_split(d[j][br][1] + bv1);
            }
            if (px0 + 8 < WW) {
                g_pk[r0 + px0+8] = pack_split(d[j][br][2] + bv0);
                g_pk[r1 + px0+8] = pack_split(d[j][br][3] + bv1);
            }
        }
    }
}

// ---------------- conv2: gated pair + BN partials ----------------
// b-frags via LDG (L1-resident), smem ~60.6 KB -> 3 blocks/SM
__global__ void __launch_bounds__(256, 3)
k_conv2(const float* __restrict__ gb, const float* __restrict__ mb,
        float* __restrict__ out) {
    extern __shared__ u32 smu[];
    u32* tile = smu;
    int* koffs = (int*)(smu + KOFF_OFF);
    float* bias = (float*)(smu + BIAS2_OFF);
    float* red  = (float*)(smu + RED2_OFF);

    int tid = threadIdx.x;
    int b  = blockIdx.z;
    int x0 = blockIdx.x * TW, y0 = blockIdx.y * TH2;

    // element-wise coalesced tile load (consecutive tid -> consecutive gx)
    for (int i = tid; i < 24*18*34; i += 256) {
        int tx = i % 34; int t = i / 34;
        int ty = t % 18; int c = t / 18;
        int gy = y0 - 1 + ty, gx = x0 - 1 + tx;
        u32 v = 0u;
        if ((unsigned)gy < HH && (unsigned)gx < WW)
            v = g_pk[((size_t)(b*24 + c)*HH + gy)*WW + gx];
        tile[c*CS2 + ty*RS2 + tx] = v;
    }
    for (int k = tid; k < K2; k += 256)
        koffs[k] = (k < K2R) ? (k/9)*CS2 + ((k%9)/3)*RS2 + (k%3) : 0;
    if (tid < 16) bias[tid] = (tid < 8) ? gb[tid] : mb[tid-8];
    __syncthreads();

    int lane = tid & 31, w = tid >> 5;
    int g = lane >> 2, tg = lane & 3;
    int s = w >> 2, wr = w & 3;

    const uint2* bfr = reinterpret_cast<const uint2*>(bfrag2);

    float s0 = 0.f, s1 = 0.f, q0 = 0.f, q1 = 0.f;

    for (int p = 0; p < 2; p++) {
        int ry0 = wr*4 + p*2;
        int baseA = ry0*RS2 + s*16 + g;
        float d[2][NT2][4];
        #pragma unroll
        for (int j = 0; j < 2; j++)
            #pragma unroll
            for (int nt = 0; nt < NT2; nt++)
                #pragma unroll
                for (int q = 0; q < 4; q++) d[j][nt][q] = 0.f;

        for (int step = 0; step < STEPS2; step++) {
            int kb = step*16 + 2*tg;
            int o0 = koffs[kb], o1 = koffs[kb+1], o2 = koffs[kb+8], o3 = koffs[kb+9];
            u32 ah[2][4], al[2][4];
            #pragma unroll
            for (int j = 0; j < 2; j++) {
                int ba = baseA + j*RS2;
                u32 e00 = tile[ba + o0],   e01 = tile[ba + o1];
                u32 e02 = tile[ba + o2],   e03 = tile[ba + o3];
                u32 e10 = tile[ba+8 + o0], e11 = tile[ba+8 + o1];
                u32 e12 = tile[ba+8 + o2], e13 = tile[ba+8 + o3];
                ah[j][0] = __byte_perm(e00, e01, 0x7632);
                ah[j][1] = __byte_perm(e10, e11, 0x7632);
                ah[j][2] = __byte_perm(e02, e03, 0x7632);
                ah[j][3] = __byte_perm(e12, e13, 0x7632);
                al[j][0] = __byte_perm(e00, e01, 0x5410);
                al[j][1] = __byte_perm(e10, e11, 0x5410);
                al[j][2] = __byte_perm(e02, e03, 0x5410);
                al[j][3] = __byte_perm(e12, e13, 0x5410);
            }
            #pragma unroll
            for (int nt = 0; nt < NT2; nt++) {
                int bi = ((step*NT2 + nt)*2)*32 + lane;
                uint2 bh = __ldg(&bfr[bi]);
                uint2 bl = __ldg(&bfr[bi + 32]);
                #pragma unroll
                for (int j = 0; j < 2; j++) {
                    mma_bf16(d[j][nt], ah[j][0], ah[j][1], ah[j][2], ah[j][3], bh.x, bh.y);
                    mma_bf16(d[j][nt], ah[j][0], ah[j][1], ah[j][2], ah[j][3], bl.x, bl.y);
                    mma_bf16(d[j][nt], al[j][0], al[j][1], al[j][2], al[j][3], bh.x, bh.y);
                }
            }
        }

        int oc0 = 2*tg;
        float bg0 = bias[oc0], bg1 = bias[oc0+1];
        float bm0 = bias[8+oc0], bm1 = bias[8+oc0+1];
        #pragma unroll
        for (int j = 0; j < 2; j++) {
            int py = y0 + ry0 + j;
            bool vy = (py < HH);
            int px0 = x0 + s*16 + g;
            size_t r0 = ((size_t)(b*8 + oc0  )*HH + py)*WW;
            size_t r1 = ((size_t)(b*8 + oc0+1)*HH + py)*WW;
            #pragma unroll
            for (int h = 0; h < 2; h++) {
                int px = px0 + h*8;
                bool vld = vy && (px < WW);
                float ga = d[j][0][2*h]   + bg0;
                float gb_ = d[j][0][2*h+1] + bg1;
                float ma = d[j][1][2*h]   + bm0;
                float mb_ = d[j][1][2*h+1] + bm1;
                float y0v = ga / (1.f + __expf(-ma));
                float y1v = gb_ / (1.f + __expf(-mb_));
                if (vld) {
                    out[r0 + px] = y0v;
                    out[r1 + px] = y1v;
                    s0 += y0v; q0 += y0v*y0v;
                    s1 += y1v; q1 += y1v*y1v;
                }
            }
        }
    }

    #pragma unroll
    for (int dlt = 4; dlt < 32; dlt <<= 1) {
        s0 += __shfl_xor_sync(0xffffffffu, s0, dlt);
        s1 += __shfl_xor_sync(0xffffffffu, s1, dlt);
        q0 += __shfl_xor_sync(0xffffffffu, q0, dlt);
        q1 += __shfl_xor_sync(0xffffffffu, q1, dlt);
    }
    if (g == 0) {
        red[w*16 + 2*tg]     = s0;
        red[w*16 + 2*tg + 1] = s1;
        red[w*16 + 8 + 2*tg]     = q0;
        red[w*16 + 8 + 2*tg + 1] = q1;
    }
    __syncthreads();
    if (tid < 16) {
        float t = 0.f;
        #pragma unroll
        for (int w2 = 0; w2 < 8; w2++) t += red[w2*16 + tid];
        int blin = (b*GY2 + blockIdx.y)*GX + blockIdx.x;
        part_buf[tid*NBLK + blin] = t;   // transposed layout
    }
}

// ---------------- BN stats: 16 warps, coalesced, deterministic ----------------
__global__ void k_stats(const float* __restrict__ gamma, const float* __restrict__ beta) {
    __shared__ double sums[16];
    int tid = threadIdx.x;
    int w = tid >> 5, lane = tid & 31;
    double a0 = 0.0, a1 = 0.0, a2 = 0.0, a3 = 0.0;
    const float* src = part_buf + w*NBLK;
    for (int i = lane; i < NBLK; i += 128) {
        a0 += (double)src[i];
        if (i + 32 < NBLK) a1 += (double)src[i + 32];
        if (i + 64 < NBLK) a2 += (double)src[i + 64];
        if (i + 96 < NBLK) a3 += (double)src[i + 96];
    }
    double acc = (a0 + a1) + (a2 + a3);
    #pragma unroll
    for (int d = 16; d > 0; d >>= 1)
        acc += __shfl_xor_sync(0xffffffffu, acc, d);
    if (lane == 0) sums[w] = acc;
    __syncthreads();
    if (tid < 8) {
        const double N = 2880000.0;
        double mean = sums[tid] / N;
        double ex2  = sums[8 + tid] / N;
        double var  = ex2 - mean * mean;
        double scale = (double)gamma[tid] / sqrt(var + 1e-5);
        double shift = (double)beta[tid] - mean * scale;
        bn_buf[tid]     = (float)scale;
        bn_buf[8 + tid] = (float)shift;
    }
}

// ---------------- normalize ----------------
__global__ void k_norm(float* __restrict__ out) {
    int i = blockIdx.x * blockDim.x + threadIdx.x;
    if (i >= 5760000) return;
    int c = (i / 22500) & 7;
    float sc = bn_buf[c], sh = bn_buf[8 + c];
    float4 v = reinterpret_cast<float4*>(out)[i];
    v.x = v.x * sc + sh;
    v.y = v.y * sc + sh;
    v.z = v.z * sc + sh;
    v.w = v.w * sc + sh;
    reinterpret_cast<float4*>(out)[i] = v;
}

// ---------------- launch ----------------
extern "C" void kernel_launch(void* const* d_in, const int* in_sizes, int n_in,
                              void* d_out, int out_size) {
    const float* x    = (const float*)d_in[0];
    const float* w5   = (const float*)d_in[1];
    const float* b5   = (const float*)d_in[2];
    const float* w10  = (const float*)d_in[3];
    const float* b10  = (const float*)d_in[4];
    const float* w15  = (const float*)d_in[5];
    const float* b15  = (const float*)d_in[6];
    const float* gw   = (const float*)d_in[7];
    const float* gb   = (const float*)d_in[8];
    const float* mw   = (const float*)d_in[9];
    const float* mb   = (const float*)d_in[10];
    const float* gamma= (const float*)d_in[11];
    const float* beta = (const float*)d_in[12];
    float* out = (float*)d_out;

    const int smem1 = SMEM1_U32 * 4;
    const int smem2 = SMEM2_U32 * 4;
    cudaFuncSetAttribute(k_conv1, cudaFuncAttributeMaxDynamicSharedMemorySize, smem1);
    cudaFuncSetAttribute(k_conv2, cudaFuncAttributeMaxDynamicSharedMemorySize, smem2);

    k_pool5   <<<(921600 + 255) / 256, 256>>>(x);
    k_poolrest<<<(332800 + 255) / 256, 256>>>();
    k_prepw   <<<32, 256>>>(w5, w10, w15, gw, mw);

    dim3 grid1(GX, GY1, 32);
    dim3 grid2(GX, GY2, 32);
    k_conv1<<<grid1, 256, smem1>>>(x, b5, b10, b15);
    k_conv2<<<grid2, 256, smem2>>>(gb, mb, out);

    k_stats<<<1, 512>>>(gamma, beta);
    k_norm <<<(5760000 + 255) / 256, 256>>>(out);
}